// round 15
// baseline (speedup 1.0000x reference)
#include <cuda_runtime.h>
#include <cuda_bf16.h>
#include <math.h>
#include <cstdint>

#define B_SZ   512
#define I_CAPS 1152
#define Q_SZ   8
#define O_CAPS 10
#define P_SZ   16
#define K_TOT  9216          // I*Q
#define N_TOT  160           // O*P
#define NT_N   20            // N_TOT/8
#define NT_Q   5             // nt per warp (quarter N-split)
#define KB16_S 576           // K_TOT/16
#define KB16_G 32            // B_SZ/16
#define MT_S   32            // B_SZ/16
#define MT_G   576           // K_TOT/16
#define KSPLIT_S 18          // 32 kb16 per split (512 k)

typedef unsigned u32;

// ---------------- static device scratch ----------------
__device__ float g_Wt[K_TOT * N_TOT];                  // [k][n] fp32
__device__ float g_b[I_CAPS * O_CAPS];
__device__ float g_c[I_CAPS * O_CAPS];
__device__ float g_spart[KSPLIT_S][B_SZ * N_TOT];
__device__ float g_v[B_SZ * N_TOT];
__device__ float g_bpart[2][I_CAPS * O_CAPS];          // parity-slot agreement partials
// A fragments: per (mt,kb): hi uint4 then lo uint4, 32 lanes each
__device__ uint4 g_afs[MT_S * KB16_S * 2 * 32];        // x   18.9 MB
__device__ uint4 g_afg[MT_G * KB16_G * 2 * 32];        // xT  18.9 MB
// B fragments: kb-major: (kb*20 + nt)*32 + lane; uint4 = {bh0,bh1,bl0,bl1}
__device__ uint4 g_bf[KB16_S * NT_N * 32];             // c.W  5.9 MB
__device__ uint4 g_vf[KB16_G * NT_N * 32];             // vT
// W in fragment order, fp32
__device__ float4 g_wf[KB16_S * NT_N * 32];            // 5.9 MB

// ---------------- helpers ----------------
__device__ __forceinline__ void split_pair(float v0, float v1, u32 &hi, u32 &lo) {
    __nv_bfloat16 h0 = __float2bfloat16(v0), h1 = __float2bfloat16(v1);
    __nv_bfloat16 l0 = __float2bfloat16(v0 - __bfloat162float(h0));
    __nv_bfloat16 l1 = __float2bfloat16(v1 - __bfloat162float(h1));
    hi = (u32)__bfloat16_as_ushort(h0) | ((u32)__bfloat16_as_ushort(h1) << 16);
    lo = (u32)__bfloat16_as_ushort(l0) | ((u32)__bfloat16_as_ushort(l1) << 16);
}
__device__ __forceinline__ void mma_bf16(float* d, u32 a0, u32 a1, u32 a2, u32 a3,
                                         u32 b0, u32 b1) {
    asm volatile(
        "mma.sync.aligned.m16n8k16.row.col.f32.bf16.bf16.f32 "
        "{%0,%1,%2,%3}, {%4,%5,%6,%7}, {%8,%9}, {%0,%1,%2,%3};"
        : "+f"(d[0]), "+f"(d[1]), "+f"(d[2]), "+f"(d[3])
        : "r"(a0), "r"(a1), "r"(a2), "r"(a3), "r"(b0), "r"(b1));
}

// ---------------- prep: Wt fp32 [k][n]; zero b; uniform c ----------------
__global__ void wt_kernel(const float* __restrict__ W) {
    int t = blockIdx.x * 256 + threadIdx.x;
    if (t < I_CAPS * O_CAPS) {
        g_b[t] = 0.0f;
        g_c[t] = 1.0f / (float)I_CAPS;
    }
    if (t >= K_TOT * N_TOT) return;
    int k = t / N_TOT, n = t - k * N_TOT;
    int i = k >> 3, q = k & 7, o = n >> 4, p = n & 15;
    g_Wt[t] = W[(i * O_CAPS + o) * (P_SZ * Q_SZ) + p * Q_SZ + q];
}

// ---------------- one-time: W -> fragment quads + iter-0 g_bf ----------------
__global__ void wprep_kernel(const float* __restrict__ W) {
    int wg = blockIdx.x * 8 + (threadIdx.x >> 5);     // kb*20 + nt
    int l = threadIdx.x & 31;
    int kb = wg / NT_N, nt = wg - kb * NT_N;
    int gid = l >> 2, tid = l & 3;
    int n = nt * 8 + gid, o = n >> 4, p = n & 15;
    int i0 = kb * 2, i1 = kb * 2 + 1;
    const float* w0 = &W[((i0 * O_CAPS + o) * P_SZ + p) * Q_SZ];
    const float* w1 = &W[((i1 * O_CAPS + o) * P_SZ + p) * Q_SZ];
    float4 wv = make_float4(w0[2 * tid], w0[2 * tid + 1], w1[2 * tid], w1[2 * tid + 1]);
    g_wf[(size_t)wg * 32 + l] = wv;
    const float cu = 1.0f / (float)I_CAPS;
    uint4 r;
    split_pair(cu * wv.x, cu * wv.y, r.x, r.z);
    split_pair(cu * wv.z, cu * wv.w, r.y, r.w);
    g_bf[(size_t)wg * 32 + l] = r;
}

// ---------------- one-time: x -> A fragments (s and G) ----------------
__global__ void xprep_kernel(const float* __restrict__ x) {
    __shared__ float st[16][129];
    const int bx = blockIdx.x, by = blockIdx.y;
    const int k0 = bx * 128, b0 = by * 16;
    const int t = threadIdx.x, w = t >> 5, l = t & 31;
    const int gid = l >> 2, tid = l & 3;

    #pragma unroll
    for (int j = 0; j < 2; j++) {
        int f = t + 256 * j;
        int row = f >> 5, c4 = f & 31;
        float4 v = *(const float4*)&x[(size_t)(b0 + row) * K_TOT + k0 + c4 * 4];
        st[row][c4 * 4 + 0] = v.x; st[row][c4 * 4 + 1] = v.y;
        st[row][c4 * 4 + 2] = v.z; st[row][c4 * 4 + 3] = v.w;
    }
    __syncthreads();

    const int j16 = w * 16;
    {   // s fragment: (mt = by, kb = bx*8 + w)
        uint4 hi, lo;
        split_pair(st[gid][j16 + 2 * tid],     st[gid][j16 + 2 * tid + 1],     hi.x, lo.x);
        split_pair(st[gid + 8][j16 + 2 * tid], st[gid + 8][j16 + 2 * tid + 1], hi.y, lo.y);
        split_pair(st[gid][j16 + 2 * tid + 8], st[gid][j16 + 2 * tid + 9],     hi.z, lo.z);
        split_pair(st[gid + 8][j16 + 2 * tid + 8], st[gid + 8][j16 + 2 * tid + 9], hi.w, lo.w);
        size_t base = (((size_t)by * KB16_S + bx * 8 + w) * 2) * 32 + l;
        g_afs[base] = hi;
        g_afs[base + 32] = lo;
    }
    {   // G fragment: (mt = bx*8 + w, bb = by)
        uint4 hi, lo;
        split_pair(st[2 * tid][j16 + gid],         st[2 * tid + 1][j16 + gid],     hi.x, lo.x);
        split_pair(st[2 * tid][j16 + gid + 8],     st[2 * tid + 1][j16 + gid + 8], hi.y, lo.y);
        split_pair(st[2 * tid + 8][j16 + gid],     st[2 * tid + 9][j16 + gid],     hi.z, lo.z);
        split_pair(st[2 * tid + 8][j16 + gid + 8], st[2 * tid + 9][j16 + gid + 8], hi.w, lo.w);
        size_t base = (((size_t)(bx * 8 + w) * KB16_G + by) * 2) * 32 + l;
        g_afg[base] = hi;
        g_afg[base + 32] = lo;
    }
}

// ---------- softmax (iters 1,2): apply bpart slots, then per-o softmax ----------
__global__ void softmax_kernel() {
    // slot validity per o: slot0 for o in {0,1,2,5,6,7}; slot1 for o in {2,3,4,7,8,9}
    const u32 mask0 = 0x0E7;   // bits 0,1,2,5,6,7
    const u32 mask1 = 0x39C;   // bits 2,3,4,7,8,9
    int t = threadIdx.x;
    for (int idx = t; idx < I_CAPS * O_CAPS; idx += 32 * O_CAPS) {
        int o = idx % O_CAPS;
        float add = 0.0f;
        if ((mask0 >> o) & 1) add += g_bpart[0][idx];
        if ((mask1 >> o) & 1) add += g_bpart[1][idx];
        g_b[idx] += add * (1.0f / (float)B_SZ);
    }
    __syncthreads();
    int o = t >> 5, lane = t & 31;
    float mx = -1e30f;
    for (int i = lane; i < I_CAPS; i += 32) mx = fmaxf(mx, g_b[i * O_CAPS + o]);
    #pragma unroll
    for (int off = 16; off; off >>= 1) mx = fmaxf(mx, __shfl_xor_sync(~0u, mx, off));
    float sum = 0.0f;
    for (int i = lane; i < I_CAPS; i += 32) sum += expf(g_b[i * O_CAPS + o] - mx);
    #pragma unroll
    for (int off = 16; off; off >>= 1) sum += __shfl_xor_sync(~0u, sum, off);
    float inv = 1.0f / sum;
    for (int i = lane; i < I_CAPS; i += 32)
        g_c[i * O_CAPS + o] = expf(g_b[i * O_CAPS + o] - mx) * inv;
}

// ---------------- per-iter (it>0): B fragments of (c .* W) ----------------
__global__ void bfrag_kernel() {
    int wg0 = (blockIdx.x * 8 + (threadIdx.x >> 5)) * 2;
    int l = threadIdx.x & 31;
    int gid = l >> 2;
    #pragma unroll
    for (int s = 0; s < 2; s++) {
        int wg = wg0 + s;
        int kb = wg / NT_N, nt = wg - kb * NT_N;
        int o = (nt * 8 + gid) >> 4;
        float c0 = g_c[(kb * 2) * O_CAPS + o], c1 = g_c[(kb * 2 + 1) * O_CAPS + o];
        float4 wv = g_wf[(size_t)wg * 32 + l];
        uint4 r;
        split_pair(c0 * wv.x, c0 * wv.y, r.x, r.z);
        split_pair(c1 * wv.z, c1 * wv.w, r.y, r.w);
        g_bf[(size_t)wg * 32 + l] = r;
    }
}

// ---------------- per-iter: B fragments of vT ----------------
__global__ void vfrag_kernel() {
    int wg = blockIdx.x * 8 + (threadIdx.x >> 5);
    int l = threadIdx.x & 31;
    int bb = wg / NT_N, nt = wg - bb * NT_N;
    int gid = l >> 2, tid = l & 3;
    int n = nt * 8 + gid;
    int b0 = bb * 16 + 2 * tid;
    uint4 r;
    split_pair(g_v[b0 * N_TOT + n],       g_v[(b0 + 1) * N_TOT + n], r.x, r.z);
    split_pair(g_v[(b0 + 8) * N_TOT + n], g_v[(b0 + 9) * N_TOT + n], r.y, r.w);
    g_vf[(size_t)wg * 32 + l] = r;
}

// ====== GEMM body: warp tile 16m x 40n, 2-deep register pipeline ======
// FUSE=0: store tile to out.  FUSE=1: contract with g_Wt into g_bpart (agreement).
template <const uint4* A, const uint4* Bsrc, int AKB, int KBN, int FUSE>
__device__ __forceinline__ void gemm_body(int mt, int nh, int kb0, float* out, int quarter) {
    const int l = threadIdx.x & 31;
    const int gid = l >> 2, tid = l & 3;

    float d[NT_Q][4];
    #pragma unroll
    for (int nt = 0; nt < NT_Q; nt++)
        #pragma unroll
        for (int e = 0; e < 4; e++) d[nt][e] = 0.0f;

    uint4 ah0, al0, b0f[NT_Q];
    uint4 ah1, al1, b1f[NT_Q];

    auto load0 = [&](int kb) {
        size_t abase = (((size_t)mt * AKB + kb) * 2) * 32 + l;
        ah0 = A[abase]; al0 = A[abase + 32];
        const uint4* Bk = &Bsrc[((size_t)kb * NT_N + nh) * 32 + l];
        #pragma unroll
        for (int nt = 0; nt < NT_Q; nt++) b0f[nt] = Bk[nt * 32];
    };
    auto load1 = [&](int kb) {
        size_t abase = (((size_t)mt * AKB + kb) * 2) * 32 + l;
        ah1 = A[abase]; al1 = A[abase + 32];
        const uint4* Bk = &Bsrc[((size_t)kb * NT_N + nh) * 32 + l];
        #pragma unroll
        for (int nt = 0; nt < NT_Q; nt++) b1f[nt] = Bk[nt * 32];
    };
    auto comp0 = [&]() {
        #pragma unroll
        for (int nt = 0; nt < NT_Q; nt++) {
            mma_bf16(d[nt], ah0.x, ah0.y, ah0.z, ah0.w, b0f[nt].x, b0f[nt].y);
            mma_bf16(d[nt], ah0.x, ah0.y, ah0.z, ah0.w, b0f[nt].z, b0f[nt].w);
            mma_bf16(d[nt], al0.x, al0.y, al0.z, al0.w, b0f[nt].x, b0f[nt].y);
        }
    };
    auto comp1 = [&]() {
        #pragma unroll
        for (int nt = 0; nt < NT_Q; nt++) {
            mma_bf16(d[nt], ah1.x, ah1.y, ah1.z, ah1.w, b1f[nt].x, b1f[nt].y);
            mma_bf16(d[nt], ah1.x, ah1.y, ah1.z, ah1.w, b1f[nt].z, b1f[nt].w);
            mma_bf16(d[nt], al1.x, al1.y, al1.z, al1.w, b1f[nt].x, b1f[nt].y);
        }
    };

    load0(kb0);
    #pragma unroll 1
    for (int kb = 0; kb < KBN; kb += 2) {
        if (kb + 1 < KBN) load1(kb0 + kb + 1);
        comp0();
        if (kb + 2 < KBN) load0(kb0 + kb + 2);
        comp1();
    }

    if (FUSE == 0) {
        int m = mt * 16 + gid;
        #pragma unroll
        for (int nt = 0; nt < NT_Q; nt++) {
            int col = (nh + nt) * 8 + tid * 2;
            *(float2*)&out[(size_t)m * N_TOT + col] = make_float2(d[nt][0], d[nt][1]);
            *(float2*)&out[(size_t)(m + 8) * N_TOT + col] = make_float2(d[nt][2], d[nt][3]);
        }
    } else {
        // agreement: b-partials per (i = 2mt+h, o). Warp cols span 3 o's.
        const int slot = quarter & 1;
        const int obase = nh >> 1;
        #pragma unroll
        for (int h = 0; h < 2; h++) {
            int row = mt * 16 + gid + 8 * h;     // G row = Wt row
            int iidx = 2 * mt + h;
            float2 wv[NT_Q];
            #pragma unroll
            for (int nt = 0; nt < NT_Q; nt++)
                wv[nt] = *(const float2*)&g_Wt[(size_t)row * N_TOT + (nh + nt) * 8 + tid * 2];
            float p0, p1, p2;
            if ((quarter & 1) == 0) {  // nt groups {0,1},{2,3},{4}
                p0 = d[0][2*h]*wv[0].x + d[0][2*h+1]*wv[0].y
                   + d[1][2*h]*wv[1].x + d[1][2*h+1]*wv[1].y;
                p1 = d[2][2*h]*wv[2].x + d[2][2*h+1]*wv[2].y
                   + d[3][2*h]*wv[3].x + d[3][2*h+1]*wv[3].y;
                p2 = d[4][2*h]*wv[4].x + d[4][2*h+1]*wv[4].y;
            } else {                    // nt groups {0},{1,2},{3,4}
                p0 = d[0][2*h]*wv[0].x + d[0][2*h+1]*wv[0].y;
                p1 = d[1][2*h]*wv[1].x + d[1][2*h+1]*wv[1].y
                   + d[2][2*h]*wv[2].x + d[2][2*h+1]*wv[2].y;
                p2 = d[3][2*h]*wv[3].x + d[3][2*h+1]*wv[3].y
                   + d[4][2*h]*wv[4].x + d[4][2*h+1]*wv[4].y;
            }
            #pragma unroll
            for (int off = 16; off; off >>= 1) {
                p0 += __shfl_xor_sync(~0u, p0, off);
                p1 += __shfl_xor_sync(~0u, p1, off);
                p2 += __shfl_xor_sync(~0u, p2, off);
            }
            if (l == 0) {
                g_bpart[slot][iidx * O_CAPS + obase]     = p0;
                g_bpart[slot][iidx * O_CAPS + obase + 1] = p1;
                g_bpart[slot][iidx * O_CAPS + obase + 2] = p2;
            }
        }
    }
}

// ---------------- s-GEMM: grid (16, 18), 256 thr, 32-kb loop ----------------
__global__ void __launch_bounds__(256, 2) s_gemm_kernel() {
    const int w = threadIdx.x >> 5;
    const int mt = (blockIdx.x >> 2) * 8 + w;
    const int nh = (blockIdx.x & 3) * NT_Q;
    gemm_body<g_afs, g_bf, KB16_S, 32, 0>(mt, nh, blockIdx.y * 32,
                                          &g_spart[blockIdx.y][0], 0);
}

// ---------------- G-GEMM: grid (288, 1); fused agreement epilogue ----------------
__global__ void __launch_bounds__(256, 2) g_gemm_kernel() {
    const int w = threadIdx.x >> 5;
    const int quarter = blockIdx.x & 3;
    const int mt = (blockIdx.x >> 2) * 8 + w;
    const int nh = quarter * NT_Q;
    gemm_body<g_afg, g_vf, KB16_G, 32, 1>(mt, nh, 0, nullptr, quarter);
}

// ---------------- reduce split-K + squash (float2 vectorized) ----------------
__global__ void squash_kernel(float* __restrict__ out, int write_out) {
    int idx = blockIdx.x * 256 + threadIdx.x;   // pair index < 40960
    int base = idx * 2;
    float2 sv = make_float2(0.0f, 0.0f);
    #pragma unroll
    for (int sp = 0; sp < KSPLIT_S; ++sp) {
        float2 p = *(const float2*)&g_spart[sp][base];
        sv.x += p.x; sv.y += p.y;
    }
    float sq = sv.x * sv.x + sv.y * sv.y;
    #pragma unroll
    for (int off = 4; off; off >>= 1)
        sq += __shfl_xor_sync(~0u, sq, off);   // reduce over 8-lane p-group
    float norm = sqrtf(sq + 1e-8f);
    float sc = (sq / (1.0f + sq)) / norm;
    float2 vv = make_float2(sv.x * sc, sv.y * sc);
    *(float2*)&g_v[base] = vv;
    if (write_out) *(float2*)&out[base] = vv;
}

// ---------------- launch ----------------
extern "C" void kernel_launch(void* const* d_in, const int* in_sizes, int n_in,
                              void* d_out, int out_size) {
    const float* x = (const float*)d_in[0];
    const float* W = (const float*)d_in[1];
    if (n_in >= 2 && in_sizes[0] == I_CAPS * O_CAPS * P_SZ * Q_SZ) {
        W = (const float*)d_in[0];
        x = (const float*)d_in[1];
    }
    float* out = (float*)d_out;

    wt_kernel<<<(K_TOT * N_TOT + 255) / 256, 256>>>(W);      // also uniform c, zero b
    wprep_kernel<<<(KB16_S * NT_N) / 8, 256>>>(W);           // also iter-0 g_bf
    xprep_kernel<<<dim3(K_TOT / 128, B_SZ / 16), 256>>>(x);

    for (int it = 0; it < 3; ++it) {
        if (it > 0) {
            softmax_kernel<<<1, 32 * O_CAPS>>>();
            bfrag_kernel<<<(KB16_S * NT_N) / 16, 256>>>();
        }
        s_gemm_kernel<<<dim3((MT_S / 8) * 4, KSPLIT_S), 256>>>();
        squash_kernel<<<(B_SZ * N_TOT / 2) / 256, 256>>>(out, it == 2 ? 1 : 0);
        if (it < 2) {
            vfrag_kernel<<<(KB16_G * NT_N) / 8, 256>>>();
            g_gemm_kernel<<<dim3((MT_G / 8) * 4, 1), 256>>>();
        }
    }
}

// round 16
// speedup vs baseline: 1.2330x; 1.2330x over previous
#include <cuda_runtime.h>
#include <cuda_bf16.h>
#include <math.h>
#include <cstdint>

#define B_SZ   512
#define I_CAPS 1152
#define Q_SZ   8
#define O_CAPS 10
#define P_SZ   16
#define K_TOT  9216          // I*Q
#define N_TOT  160           // O*P
#define NT_N   20            // N_TOT/8
#define NT_Q   5             // nt per warp (quarter N-split)
#define KB16_S 576           // K_TOT/16
#define KB16_G 32            // B_SZ/16
#define MT_S   32            // B_SZ/16
#define MT_G   576           // K_TOT/16
#define KSPLIT_S 18          // 32 kb16 per split (512 k)
#define BSPLIT_G 1

typedef unsigned u32;

// ---------------- static device scratch ----------------
__device__ float g_Wt[K_TOT * N_TOT];                  // [k][n] fp32
__device__ float g_b[I_CAPS * O_CAPS];
__device__ float g_c[I_CAPS * O_CAPS];
__device__ float g_spart[KSPLIT_S][B_SZ * N_TOT];
__device__ float g_v[B_SZ * N_TOT];
__device__ float g_Gpart[BSPLIT_G][K_TOT * N_TOT];
// A fragments: per (mt,kb): hi uint4 then lo uint4, 32 lanes each
__device__ uint4 g_afs[MT_S * KB16_S * 2 * 32];        // x   18.9 MB
__device__ uint4 g_afg[MT_G * KB16_G * 2 * 32];        // xT  18.9 MB
// B fragments: kb-major: (kb*20 + nt)*32 + lane; uint4 = {bh0,bh1,bl0,bl1}
__device__ uint4 g_bf[KB16_S * NT_N * 32];             // c.W  5.9 MB
__device__ uint4 g_vf[KB16_G * NT_N * 32];             // vT
// W in fragment order, fp32
__device__ float4 g_wf[KB16_S * NT_N * 32];            // 5.9 MB

// ---------------- helpers ----------------
__device__ __forceinline__ void split_pair(float v0, float v1, u32 &hi, u32 &lo) {
    __nv_bfloat16 h0 = __float2bfloat16(v0), h1 = __float2bfloat16(v1);
    __nv_bfloat16 l0 = __float2bfloat16(v0 - __bfloat162float(h0));
    __nv_bfloat16 l1 = __float2bfloat16(v1 - __bfloat162float(h1));
    hi = (u32)__bfloat16_as_ushort(h0) | ((u32)__bfloat16_as_ushort(h1) << 16);
    lo = (u32)__bfloat16_as_ushort(l0) | ((u32)__bfloat16_as_ushort(l1) << 16);
}
__device__ __forceinline__ void mma_bf16(float* d, u32 a0, u32 a1, u32 a2, u32 a3,
                                         u32 b0, u32 b1) {
    asm volatile(
        "mma.sync.aligned.m16n8k16.row.col.f32.bf16.bf16.f32 "
        "{%0,%1,%2,%3}, {%4,%5,%6,%7}, {%8,%9}, {%0,%1,%2,%3};"
        : "+f"(d[0]), "+f"(d[1]), "+f"(d[2]), "+f"(d[3])
        : "r"(a0), "r"(a1), "r"(a2), "r"(a3), "r"(b0), "r"(b1));
}

// ---------------- prep: Wt fp32 [k][n]; zero b; uniform c ----------------
__global__ void wt_kernel(const float* __restrict__ W) {
    int t = blockIdx.x * 256 + threadIdx.x;
    if (t < I_CAPS * O_CAPS) {
        g_b[t] = 0.0f;
        g_c[t] = 1.0f / (float)I_CAPS;
    }
    if (t >= K_TOT * N_TOT) return;
    int k = t / N_TOT, n = t - k * N_TOT;
    int i = k >> 3, q = k & 7, o = n >> 4, p = n & 15;
    g_Wt[t] = W[(i * O_CAPS + o) * (P_SZ * Q_SZ) + p * Q_SZ + q];
}

// ---------------- one-time: W -> fragment quads + iter-0 g_bf ----------------
__global__ void wprep_kernel(const float* __restrict__ W) {
    int wg = blockIdx.x * 8 + (threadIdx.x >> 5);     // kb*20 + nt
    int l = threadIdx.x & 31;
    int kb = wg / NT_N, nt = wg - kb * NT_N;
    int gid = l >> 2, tid = l & 3;
    int n = nt * 8 + gid, o = n >> 4, p = n & 15;
    int i0 = kb * 2, i1 = kb * 2 + 1;
    const float* w0 = &W[((i0 * O_CAPS + o) * P_SZ + p) * Q_SZ];
    const float* w1 = &W[((i1 * O_CAPS + o) * P_SZ + p) * Q_SZ];
    float4 wv = make_float4(w0[2 * tid], w0[2 * tid + 1], w1[2 * tid], w1[2 * tid + 1]);
    g_wf[(size_t)wg * 32 + l] = wv;
    const float cu = 1.0f / (float)I_CAPS;
    uint4 r;
    split_pair(cu * wv.x, cu * wv.y, r.x, r.z);
    split_pair(cu * wv.z, cu * wv.w, r.y, r.w);
    g_bf[(size_t)wg * 32 + l] = r;
}

// ---------------- one-time: x -> A fragments (s and G) ----------------
__global__ void xprep_kernel(const float* __restrict__ x) {
    __shared__ float st[16][129];
    const int bx = blockIdx.x, by = blockIdx.y;
    const int k0 = bx * 128, b0 = by * 16;
    const int t = threadIdx.x, w = t >> 5, l = t & 31;
    const int gid = l >> 2, tid = l & 3;

    #pragma unroll
    for (int j = 0; j < 2; j++) {
        int f = t + 256 * j;
        int row = f >> 5, c4 = f & 31;
        float4 v = *(const float4*)&x[(size_t)(b0 + row) * K_TOT + k0 + c4 * 4];
        st[row][c4 * 4 + 0] = v.x; st[row][c4 * 4 + 1] = v.y;
        st[row][c4 * 4 + 2] = v.z; st[row][c4 * 4 + 3] = v.w;
    }
    __syncthreads();

    const int j16 = w * 16;
    {   // s fragment: (mt = by, kb = bx*8 + w)
        uint4 hi, lo;
        split_pair(st[gid][j16 + 2 * tid],     st[gid][j16 + 2 * tid + 1],     hi.x, lo.x);
        split_pair(st[gid + 8][j16 + 2 * tid], st[gid + 8][j16 + 2 * tid + 1], hi.y, lo.y);
        split_pair(st[gid][j16 + 2 * tid + 8], st[gid][j16 + 2 * tid + 9],     hi.z, lo.z);
        split_pair(st[gid + 8][j16 + 2 * tid + 8], st[gid + 8][j16 + 2 * tid + 9], hi.w, lo.w);
        size_t base = (((size_t)by * KB16_S + bx * 8 + w) * 2) * 32 + l;
        g_afs[base] = hi;
        g_afs[base + 32] = lo;
    }
    {   // G fragment: (mt = bx*8 + w, bb = by)
        uint4 hi, lo;
        split_pair(st[2 * tid][j16 + gid],         st[2 * tid + 1][j16 + gid],     hi.x, lo.x);
        split_pair(st[2 * tid][j16 + gid + 8],     st[2 * tid + 1][j16 + gid + 8], hi.y, lo.y);
        split_pair(st[2 * tid + 8][j16 + gid],     st[2 * tid + 9][j16 + gid],     hi.z, lo.z);
        split_pair(st[2 * tid + 8][j16 + gid + 8], st[2 * tid + 9][j16 + gid + 8], hi.w, lo.w);
        size_t base = (((size_t)(bx * 8 + w) * KB16_G + by) * 2) * 32 + l;
        g_afg[base] = hi;
        g_afg[base + 32] = lo;
    }
}

// ---------------- softmax over i (one warp per o); iters 1,2 only ----------------
__global__ void softmax_kernel() {
    int o = threadIdx.x >> 5, lane = threadIdx.x & 31;
    float mx = -1e30f;
    for (int i = lane; i < I_CAPS; i += 32) mx = fmaxf(mx, g_b[i * O_CAPS + o]);
    #pragma unroll
    for (int off = 16; off; off >>= 1) mx = fmaxf(mx, __shfl_xor_sync(~0u, mx, off));
    float sum = 0.0f;
    for (int i = lane; i < I_CAPS; i += 32) sum += expf(g_b[i * O_CAPS + o] - mx);
    #pragma unroll
    for (int off = 16; off; off >>= 1) sum += __shfl_xor_sync(~0u, sum, off);
    float inv = 1.0f / sum;
    for (int i = lane; i < I_CAPS; i += 32)
        g_c[i * O_CAPS + o] = expf(g_b[i * O_CAPS + o] - mx) * inv;
}

// ---------------- per-iter (it>0): B fragments of (c .* W); 2 wgs per warp ----------------
__global__ void bfrag_kernel() {
    int wg0 = (blockIdx.x * 8 + (threadIdx.x >> 5)) * 2;   // pairs of wg, < 11520
    int l = threadIdx.x & 31;
    int gid = l >> 2;
    #pragma unroll
    for (int s = 0; s < 2; s++) {
        int wg = wg0 + s;
        int kb = wg / NT_N, nt = wg - kb * NT_N;
        int o = (nt * 8 + gid) >> 4;
        float c0 = g_c[(kb * 2) * O_CAPS + o], c1 = g_c[(kb * 2 + 1) * O_CAPS + o];
        float4 wv = g_wf[(size_t)wg * 32 + l];
        uint4 r;
        split_pair(c0 * wv.x, c0 * wv.y, r.x, r.z);
        split_pair(c1 * wv.z, c1 * wv.w, r.y, r.w);
        g_bf[(size_t)wg * 32 + l] = r;
    }
}

// ---------------- per-iter: B fragments of vT ----------------
__global__ void vfrag_kernel() {
    int wg = blockIdx.x * 8 + (threadIdx.x >> 5);     // bb*20 + nt, < 640
    int l = threadIdx.x & 31;
    int bb = wg / NT_N, nt = wg - bb * NT_N;
    int gid = l >> 2, tid = l & 3;
    int n = nt * 8 + gid;
    int b0 = bb * 16 + 2 * tid;
    uint4 r;
    split_pair(g_v[b0 * N_TOT + n],       g_v[(b0 + 1) * N_TOT + n], r.x, r.z);
    split_pair(g_v[(b0 + 8) * N_TOT + n], g_v[(b0 + 9) * N_TOT + n], r.y, r.w);
    g_vf[(size_t)wg * 32 + l] = r;
}

// ====== GEMM body: warp tile 16m x 40n, 2-deep register pipeline, no barriers ======
// TERMS=3: D = AhBh + AhBl + AlBh (full split).  TERMS=2: D = AhBh + AlBh (= A·Bh).
template <const uint4* A, const uint4* Bsrc, int AKB, int KBN, int TERMS>
__device__ __forceinline__ void gemm_body(int mt, int nh, int kb0, float* out) {
    const int l = threadIdx.x & 31;
    const int gid = l >> 2, tid = l & 3;

    float d[NT_Q][4];
    #pragma unroll
    for (int nt = 0; nt < NT_Q; nt++)
        #pragma unroll
        for (int e = 0; e < 4; e++) d[nt][e] = 0.0f;

    uint4 ah0, al0, b0f[NT_Q];
    uint4 ah1, al1, b1f[NT_Q];

    auto load0 = [&](int kb) {
        size_t abase = (((size_t)mt * AKB + kb) * 2) * 32 + l;
        ah0 = A[abase]; al0 = A[abase + 32];
        const uint4* Bk = &Bsrc[((size_t)kb * NT_N + nh) * 32 + l];
        #pragma unroll
        for (int nt = 0; nt < NT_Q; nt++) b0f[nt] = Bk[nt * 32];
    };
    auto load1 = [&](int kb) {
        size_t abase = (((size_t)mt * AKB + kb) * 2) * 32 + l;
        ah1 = A[abase]; al1 = A[abase + 32];
        const uint4* Bk = &Bsrc[((size_t)kb * NT_N + nh) * 32 + l];
        #pragma unroll
        for (int nt = 0; nt < NT_Q; nt++) b1f[nt] = Bk[nt * 32];
    };
    auto comp0 = [&]() {
        #pragma unroll
        for (int nt = 0; nt < NT_Q; nt++) {
            mma_bf16(d[nt], ah0.x, ah0.y, ah0.z, ah0.w, b0f[nt].x, b0f[nt].y);
            if (TERMS == 3)
                mma_bf16(d[nt], ah0.x, ah0.y, ah0.z, ah0.w, b0f[nt].z, b0f[nt].w);
            mma_bf16(d[nt], al0.x, al0.y, al0.z, al0.w, b0f[nt].x, b0f[nt].y);
        }
    };
    auto comp1 = [&]() {
        #pragma unroll
        for (int nt = 0; nt < NT_Q; nt++) {
            mma_bf16(d[nt], ah1.x, ah1.y, ah1.z, ah1.w, b1f[nt].x, b1f[nt].y);
            if (TERMS == 3)
                mma_bf16(d[nt], ah1.x, ah1.y, ah1.z, ah1.w, b1f[nt].z, b1f[nt].w);
            mma_bf16(d[nt], al1.x, al1.y, al1.z, al1.w, b1f[nt].x, b1f[nt].y);
        }
    };

    load0(kb0);
    #pragma unroll 1
    for (int kb = 0; kb < KBN; kb += 2) {
        if (kb + 1 < KBN) load1(kb0 + kb + 1);
        comp0();
        if (kb + 2 < KBN) load0(kb0 + kb + 2);
        comp1();
    }

    int m = mt * 16 + gid;
    #pragma unroll
    for (int nt = 0; nt < NT_Q; nt++) {
        int col = (nh + nt) * 8 + tid * 2;
        *(float2*)&out[(size_t)m * N_TOT + col] = make_float2(d[nt][0], d[nt][1]);
        *(float2*)&out[(size_t)(m + 8) * N_TOT + col] = make_float2(d[nt][2], d[nt][3]);
    }
}

// ---------------- s-GEMM: grid (16, 18), 256 thr, 32-kb loop ----------------
template <int TERMS>
__global__ void __launch_bounds__(256, 2) s_gemm_kernel() {
    const int w = threadIdx.x >> 5;
    const int mt = (blockIdx.x >> 2) * 8 + w;
    const int nh = (blockIdx.x & 3) * NT_Q;
    gemm_body<g_afs, g_bf, KB16_S, 32, TERMS>(mt, nh, blockIdx.y * 32,
                                              &g_spart[blockIdx.y][0]);
}

// ---------------- G-GEMM: grid (288, 1), 256 thr, 32-bb loop, 2-term ----------------
__global__ void __launch_bounds__(256, 2) g_gemm_kernel() {
    const int w = threadIdx.x >> 5;
    const int mt = (blockIdx.x >> 2) * 8 + w;
    const int nh = (blockIdx.x & 3) * NT_Q;
    gemm_body<g_afg, g_vf, KB16_G, 32, 2>(mt, nh, 0, &g_Gpart[0][0]);
}

// ---------------- reduce split-K + squash (float2 vectorized) ----------------
__global__ void squash_kernel(float* __restrict__ out, int write_out) {
    int idx = blockIdx.x * 256 + threadIdx.x;   // pair index < 40960
    int base = idx * 2;
    float2 sv = make_float2(0.0f, 0.0f);
    #pragma unroll
    for (int sp = 0; sp < KSPLIT_S; ++sp) {
        float2 p = *(const float2*)&g_spart[sp][base];
        sv.x += p.x; sv.y += p.y;
    }
    float sq = sv.x * sv.x + sv.y * sv.y;
    #pragma unroll
    for (int off = 4; off; off >>= 1)
        sq += __shfl_xor_sync(~0u, sq, off);   // reduce over 8-lane p-group
    float norm = sqrtf(sq + 1e-8f);
    float sc = (sq / (1.0f + sq)) / norm;
    float2 vv = make_float2(sv.x * sc, sv.y * sc);
    *(float2*)&g_v[base] = vv;
    if (write_out) *(float2*)&out[base] = vv;
}

// ---------------- b[i,o] += (1/512) * sum over 8x16 block of Wt .* Gpart ----------------
__global__ void b_update_kernel() {
    int w = (blockIdx.x * 256 + threadIdx.x) >> 5;
    int lane = threadIdx.x & 31;
    if (w >= I_CAPS * O_CAPS) return;
    int i = w / O_CAPS, o = w - i * O_CAPS;
    int row = i * 8 + (lane >> 2);
    int col = o * 16 + (lane & 3) * 4;
    int base = row * N_TOT + col;
    float4 wv = *(const float4*)&g_Wt[base];
    float4 g0 = *(const float4*)&g_Gpart[0][base];
    float dd = wv.x * g0.x + wv.y * g0.y + wv.z * g0.z + wv.w * g0.w;
    #pragma unroll
    for (int off = 16; off; off >>= 1) dd += __shfl_xor_sync(~0u, dd, off);
    if (lane == 0) g_b[w] += dd * (1.0f / (float)B_SZ);
}

// ---------------- launch ----------------
extern "C" void kernel_launch(void* const* d_in, const int* in_sizes, int n_in,
                              void* d_out, int out_size) {
    const float* x = (const float*)d_in[0];
    const float* W = (const float*)d_in[1];
    if (n_in >= 2 && in_sizes[0] == I_CAPS * O_CAPS * P_SZ * Q_SZ) {
        W = (const float*)d_in[0];
        x = (const float*)d_in[1];
    }
    float* out = (float*)d_out;

    wt_kernel<<<(K_TOT * N_TOT + 255) / 256, 256>>>(W);      // also uniform c, zero b
    wprep_kernel<<<(KB16_S * NT_N) / 8, 256>>>(W);           // also iter-0 g_bf
    xprep_kernel<<<dim3(K_TOT / 128, B_SZ / 16), 256>>>(x);

    for (int it = 0; it < 3; ++it) {
        if (it > 0) {
            softmax_kernel<<<1, 32 * O_CAPS>>>();
            bfrag_kernel<<<(KB16_S * NT_N) / 16, 256>>>();
        }
        if (it == 2)
            s_gemm_kernel<3><<<dim3((MT_S / 8) * 4, KSPLIT_S), 256>>>();
        else
            s_gemm_kernel<2><<<dim3((MT_S / 8) * 4, KSPLIT_S), 256>>>();
        squash_kernel<<<(B_SZ * N_TOT / 2) / 256, 256>>>(out, it == 2 ? 1 : 0);
        if (it < 2) {
            vfrag_kernel<<<(KB16_G * NT_N) / 8, 256>>>();
            g_gemm_kernel<<<dim3((MT_G / 8) * 4, 1), 256>>>();
            b_update_kernel<<<(I_CAPS * O_CAPS * 32 + 255) / 256, 256>>>();
        }
    }
}